// round 13
// baseline (speedup 1.0000x reference)
#include <cuda_runtime.h>
#include <math.h>

#define BB   8
#define CIN  256
#define LIN  2046
#define LPAD 2048
#define IC   64
#define OCH  128
#define BNEPS 1e-5f
#define MT   32

typedef unsigned long long u64;
__device__ __forceinline__ u64 pk2(float x, float y) { u64 r; asm("mov.b64 %0,{%1,%2};" : "=l"(r) : "f"(x), "f"(y)); return r; }
__device__ __forceinline__ float2 up2(u64 v) { float2 r; asm("mov.b64 {%0,%1},%2;" : "=f"(r.x), "=f"(r.y) : "l"(v)); return r; }
__device__ __forceinline__ void fma2(u64& d, u64 a, u64 b) { asm("fma.rn.f32x2 %0,%1,%2,%0;" : "+l"(d) : "l"(a), "l"(b)); }

// ---------------- scratch ----------------
__device__ float g_pre1[BB*IC*LPAD];
__device__ float g_pre2[BB*IC*LPAD];
__device__ float g_preA[BB*IC*LPAD];
__device__ float g_preB[BB*IC*LPAD];
__device__ float g_feat1[BB*IC*LPAD];
__device__ float g_feat2[BB*IC*LPAD];
__device__ float g_saconv[BB*IC*LPAD];
__device__ float g_scconv[BB*IC*LPAD];
__device__ float g_safeat[BB*IC*LPAD];
__device__ float g_scfeat[BB*IC*LPAD];
__device__ float g_qp[BB*8*LPAD];
__device__ float g_kp[BB*8*LPAD];
__device__ float g_v[BB*IC*LPAD];
__device__ float g_came[BB*IC*IC];
__device__ float g_msum[BB*IC];
__device__ float g_sS[4*IC];
__device__ float g_sSS[4*IC];
__device__ unsigned g_kmax[BB*8];

__device__ __forceinline__ float* selbuf(int s) {
    switch (s) {
        case 0: return g_pre1;   case 1: return g_pre2;
        case 2: return g_preA;   case 3: return g_preB;
        case 4: return g_feat1;  case 5: return g_feat2;
        case 6: return g_saconv; case 7: return g_scconv;
        case 8: return g_safeat; default: return g_scfeat;
    }
}

__global__ void k_zeroall() {
    int idx = blockIdx.x * 256 + threadIdx.x;
    if (idx < BB*IC*IC) g_came[idx] = 0.f;
    if (idx < 4*IC) { g_sS[idx] = 0.f; g_sSS[idx] = 0.f; }
    if (idx < BB*8) g_kmax[idx] = 0u;
}

// ---------- conv1x1 from x: one block does ALL 128 outputs for a 64-l tile ----------
__global__ __launch_bounds__(256) void k_convx(const float* __restrict__ x,
                                               const float* __restrict__ W5a,
                                               const float* __restrict__ W5c) {
    int b = blockIdx.z, l0 = blockIdx.x * 64;
    __shared__ float Ws[16][132], Xs[16][68];
    int tid = threadIdx.x, ty = tid / 16, tx = tid % 16;   // o = ty*8.., l = tx*4..
    u64 acc[8][2] = {};
    const float* xb = x + (size_t)b * CIN * LIN;
    for (int kc = 0; kc < CIN; kc += 16) {
#pragma unroll
        for (int t = 0; t < 8; t++) {
            int i = tid + t * 256, k = i / 128, o = i % 128;
            const float* Wp = (o < IC) ? (W5a + o * CIN) : (W5c + (o - IC) * CIN);
            Ws[k][o] = Wp[kc + k];
        }
#pragma unroll
        for (int t = 0; t < 4; t++) {
            int i = tid + t * 256, k = i / 64, l = i % 64;
            int gl = l0 + l;
            Xs[k][l] = (gl < LIN) ? xb[(size_t)(kc + k) * LIN + gl] : 0.f;
        }
        __syncthreads();
#pragma unroll
        for (int k = 0; k < 16; k++) {
            float4 a0 = *(float4*)&Ws[k][ty * 8];
            float4 a1 = *(float4*)&Ws[k][ty * 8 + 4];
            u64 b01 = *(u64*)&Xs[k][tx * 4];
            u64 b23 = *(u64*)&Xs[k][tx * 4 + 2];
            u64 d0 = pk2(a0.x, a0.x), d1 = pk2(a0.y, a0.y), d2 = pk2(a0.z, a0.z), d3 = pk2(a0.w, a0.w);
            u64 d4 = pk2(a1.x, a1.x), d5 = pk2(a1.y, a1.y), d6 = pk2(a1.z, a1.z), d7 = pk2(a1.w, a1.w);
            fma2(acc[0][0], d0, b01); fma2(acc[0][1], d0, b23);
            fma2(acc[1][0], d1, b01); fma2(acc[1][1], d1, b23);
            fma2(acc[2][0], d2, b01); fma2(acc[2][1], d2, b23);
            fma2(acc[3][0], d3, b01); fma2(acc[3][1], d3, b23);
            fma2(acc[4][0], d4, b01); fma2(acc[4][1], d4, b23);
            fma2(acc[5][0], d5, b01); fma2(acc[5][1], d5, b23);
            fma2(acc[6][0], d6, b01); fma2(acc[6][1], d6, b23);
            fma2(acc[7][0], d7, b01); fma2(acc[7][1], d7, b23);
        }
        __syncthreads();
    }
#pragma unroll
    for (int i = 0; i < 8; i++) {
        int o = ty * 8 + i;
        int slot = (o < IC) ? 0 : 1;
        int ch = o & (IC - 1);
        float* dst = (o < IC) ? (g_pre1 + ((size_t)b * IC + ch) * LPAD)
                              : (g_pre2 + ((size_t)b * IC + ch) * LPAD);
        float2 p0 = up2(acc[i][0]), p1 = up2(acc[i][1]);
        float vv[4] = {p0.x, p0.y, p1.x, p1.y};
        float s = 0.f, ss = 0.f;
#pragma unroll
        for (int j = 0; j < 4; j++) {
            int l = l0 + tx * 4 + j;
            if (l < LIN) { dst[l + 1] = vv[j]; s += vv[j]; ss += vv[j] * vv[j]; }
        }
#pragma unroll
        for (int off = 8; off > 0; off >>= 1) {
            s  += __shfl_xor_sync(0xffffffffu, s, off);
            ss += __shfl_xor_sync(0xffffffffu, ss, off);
        }
        if (tx == 0) {
            atomicAdd(&g_sS[slot * IC + ch], s);
            atomicAdd(&g_sSS[slot * IC + ch], ss);
        }
    }
}

// ---------- BN + ReLU (float4), dual-slot via grid.z ----------
__global__ void k_bnrelu01(const float* __restrict__ g0, const float* __restrict__ bia0,
                           const float* __restrict__ g1, const float* __restrict__ bia1) {
    int z = blockIdx.z;
    const float4* pre = (const float4*)selbuf(z);
    float4* out = (float4*)selbuf(4 + z);
    const float* g = z ? g1 : g0;
    const float* bia = z ? bia1 : bia0;
    int idx = blockIdx.x * 256 + threadIdx.x;
    int l4 = idx & 511;
    int c = (idx >> 9) & (IC - 1);
    float4 v = pre[idx];
    if (l4 == 0) v.x = 0.f;
    if (l4 == 511) v.w = 0.f;
    float N = (float)(BB * LPAD);
    float mu = g_sS[z * IC + c] / N;
    float rs = rsqrtf(g_sSS[z * IC + c] / N - mu * mu + BNEPS);
    float sc = rs * g[c], sb = bia[c] - mu * sc;
    float4 r;
    r.x = fmaxf(v.x * sc + sb, 0.f); r.y = fmaxf(v.y * sc + sb, 0.f);
    r.z = fmaxf(v.z * sc + sb, 0.f); r.w = fmaxf(v.w * sc + sb, 0.f);
    out[idx] = r;
}

__global__ void k_bnrelu(int psel, int osel, const float* __restrict__ g,
                         const float* __restrict__ bia, int slot) {
    const float4* pre = (const float4*)selbuf(psel);
    float4* out = (float4*)selbuf(osel);
    int idx = blockIdx.x * 256 + threadIdx.x;
    int c = (idx >> 9) & (IC - 1);
    float4 v = pre[idx];
    float N = (float)(BB * LPAD);
    float mu = g_sS[slot * IC + c] / N;
    float rs = rsqrtf(g_sSS[slot * IC + c] / N - mu * mu + BNEPS);
    float sc = rs * g[c], sb = bia[c] - mu * sc;
    float4 r;
    r.x = fmaxf(v.x * sc + sb, 0.f); r.y = fmaxf(v.y * sc + sb, 0.f);
    r.z = fmaxf(v.z * sc + sb, 0.f); r.w = fmaxf(v.w * sc + sb, 0.f);
    out[idx] = r;
}

// ---------- q/k/v from feat1: 80 x 64 tile, planar q/k stores ----------
__global__ __launch_bounds__(256) void k_qkv(const float* __restrict__ Wq, const float* __restrict__ bq,
                                             const float* __restrict__ Wk, const float* __restrict__ bk,
                                             const float* __restrict__ Wv, const float* __restrict__ bvw) {
    int b = blockIdx.y, l0 = blockIdx.x * 64;
    __shared__ float Ws[16][84], Xs[16][68];
    int tid = threadIdx.x, ty = tid / 16, tx = tid % 16;   // o = ty*5.., l = tx*4..
    u64 acc[5][2] = {};
    const float* f1 = g_feat1 + (size_t)b * IC * LPAD;
    for (int kc = 0; kc < 64; kc += 16) {
#pragma unroll
        for (int t = 0; t < 5; t++) {
            int i = tid + t * 256;
            int k = i / 80, o = i % 80;
            float v;
            if (o < 8)       v = Wq[o * IC + kc + k];
            else if (o < 16) v = Wk[(o - 8) * IC + kc + k];
            else             v = Wv[(o - 16) * IC + kc + k];
            Ws[k][o] = v;
        }
        {
            int k = tid / 16, l4 = (tid % 16) * 4;
            float4 v = *(const float4*)(f1 + (size_t)(kc + k) * LPAD + l0 + l4);
            Xs[k][l4] = v.x; Xs[k][l4 + 1] = v.y; Xs[k][l4 + 2] = v.z; Xs[k][l4 + 3] = v.w;
        }
        __syncthreads();
#pragma unroll
        for (int k = 0; k < 16; k++) {
            u64 b0 = *(u64*)&Xs[k][tx * 4];
            u64 b1 = *(u64*)&Xs[k][tx * 4 + 2];
#pragma unroll
            for (int i = 0; i < 5; i++) {
                float a = Ws[k][ty * 5 + i];
                u64 ap = pk2(a, a);
                fma2(acc[i][0], ap, b0); fma2(acc[i][1], ap, b1);
            }
        }
        __syncthreads();
    }
#pragma unroll
    for (int i = 0; i < 5; i++) {
        int o = ty * 5 + i;
        float bias = (o < 8) ? bq[o] : ((o < 16) ? bk[o - 8] : bvw[o - 16]);
        float2 p0 = up2(acc[i][0]), p1 = up2(acc[i][1]);
        float4 r = {p0.x + bias, p0.y + bias, p1.x + bias, p1.y + bias};
        if (o < 8) {
            *(float4*)(g_qp + ((size_t)(b * 8 + o)) * LPAD + l0 + tx * 4) = r;
        } else if (o < 16) {
            *(float4*)(g_kp + ((size_t)(b * 8 + o - 8)) * LPAD + l0 + tx * 4) = r;
            float ka = fmaxf(fmaxf(fabsf(r.x), fabsf(r.y)), fmaxf(fabsf(r.z), fabsf(r.w)));
            atomicMax(&g_kmax[b * 8 + (o - 8)], __float_as_uint(ka));
        } else {
            *(float4*)(g_v + ((size_t)b * IC + (o - 16)) * LPAD + l0 + tx * 4) = r;
        }
    }
}

// ---------- PAM fused (flash-style, fixed upper-bound max) ----------
__global__ __launch_bounds__(256) void k_pamout(const float* __restrict__ gamma) {
    int b = blockIdx.y, l0 = blockIdx.x * 128;   // grid (16, 8)
    __shared__ u64  ksp[4][36];
    __shared__ float psT[MT][132];
    __shared__ float vsmT[MT][68];
    __shared__ float sumP[2][128];
    int tid = threadIdx.x;
    int lq = tid & 127, mh = tid >> 7;
    float qj[8];
#pragma unroll
    for (int j = 0; j < 8; j++) qj[j] = g_qp[((size_t)(b * 8 + j)) * LPAD + l0 + lq];
    u64 qp[4] = { pk2(qj[0], qj[1]), pk2(qj[2], qj[3]), pk2(qj[4], qj[5]), pk2(qj[6], qj[7]) };
    float Mv = 0.f;
#pragma unroll
    for (int j = 0; j < 8; j++) Mv += fabsf(qj[j]) * __uint_as_float(g_kmax[b * 8 + j]);
    float lsum = 0.f;
    int cy = (tid >> 5) * 8, lx = (tid & 31) * 4;
    u64 acc[8][2] = {};
    const float* vb = g_v + (size_t)b * IC * LPAD;
    for (int m0 = 0; m0 < LPAD; m0 += MT) {
        if (tid < 128) {
            int p = tid >> 5, m = tid & 31;
            float kx = g_kp[((size_t)(b * 8 + 2 * p)) * LPAD + m0 + m];
            float ky = g_kp[((size_t)(b * 8 + 2 * p + 1)) * LPAD + m0 + m];
            ksp[p][m] = pk2(kx, ky);
        }
#pragma unroll
        for (int t = 0; t < 2; t++) {
            int i = tid + t * 256;
            int c = i >> 3, m4 = (i & 7) * 4;
            float4 v = *(const float4*)(vb + (size_t)c * LPAD + m0 + m4);
            vsmT[m4 + 0][c] = v.x; vsmT[m4 + 1][c] = v.y;
            vsmT[m4 + 2][c] = v.z; vsmT[m4 + 3][c] = v.w;
        }
        __syncthreads();
#pragma unroll
        for (int t = 0; t < 16; t++) {
            int m = mh * 16 + t;
            u64 s2 = 0ull;
            fma2(s2, qp[0], ksp[0][m]); fma2(s2, qp[1], ksp[1][m]);
            fma2(s2, qp[2], ksp[2][m]); fma2(s2, qp[3], ksp[3][m]);
            float2 sv = up2(s2);
            float p = __expf(sv.x + sv.y - Mv);
            psT[m][lq] = p;
            lsum += p;
        }
        __syncthreads();
#pragma unroll 4
        for (int m = 0; m < MT; m++) {
            u64 p01 = *(u64*)&psT[m][lx];
            u64 p23 = *(u64*)&psT[m][lx + 2];
            float4 v0 = *(float4*)&vsmT[m][cy];
            float4 v1 = *(float4*)&vsmT[m][cy + 4];
            u64 d0 = pk2(v0.x, v0.x), d1 = pk2(v0.y, v0.y), d2 = pk2(v0.z, v0.z), d3 = pk2(v0.w, v0.w);
            u64 d4 = pk2(v1.x, v1.x), d5 = pk2(v1.y, v1.y), d6 = pk2(v1.z, v1.z), d7 = pk2(v1.w, v1.w);
            fma2(acc[0][0], d0, p01); fma2(acc[0][1], d0, p23);
            fma2(acc[1][0], d1, p01); fma2(acc[1][1], d1, p23);
            fma2(acc[2][0], d2, p01); fma2(acc[2][1], d2, p23);
            fma2(acc[3][0], d3, p01); fma2(acc[3][1], d3, p23);
            fma2(acc[4][0], d4, p01); fma2(acc[4][1], d4, p23);
            fma2(acc[5][0], d5, p01); fma2(acc[5][1], d5, p23);
            fma2(acc[6][0], d6, p01); fma2(acc[6][1], d6, p23);
            fma2(acc[7][0], d7, p01); fma2(acc[7][1], d7, p23);
        }
        __syncthreads();
    }
    sumP[mh][lq] = lsum;
    __syncthreads();
    float i0 = 1.f / (sumP[0][lx + 0] + sumP[1][lx + 0]);
    float i1 = 1.f / (sumP[0][lx + 1] + sumP[1][lx + 1]);
    float i2 = 1.f / (sumP[0][lx + 2] + sumP[1][lx + 2]);
    float i3 = 1.f / (sumP[0][lx + 3] + sumP[1][lx + 3]);
    float gm = gamma[0];
#pragma unroll
    for (int i = 0; i < 8; i++) {
        size_t row = ((size_t)b * IC + cy + i) * LPAD + l0 + lx;
        float2 a0 = up2(acc[i][0]), a1 = up2(acc[i][1]);
        float4 f = *(const float4*)(g_feat1 + row);
        float4 r;
        r.x = gm * a0.x * i0 + f.x; r.y = gm * a0.y * i1 + f.y;
        r.z = gm * a1.x * i2 + f.z; r.w = gm * a1.y * i3 + f.w;
        *(float4*)(g_safeat + row) = r;
    }
}

// ---------- CAM energy ----------
__global__ __launch_bounds__(256) void k_came() {
    int b = blockIdx.x, ls = blockIdx.y;
    __shared__ float Fs[64][33];
    int tid = threadIdx.x;
    int cy = (tid / 16) * 4, dx = (tid % 16) * 4;
    float acc[4][4] = {};
    const float* f2 = g_feat2 + (size_t)b * IC * LPAD;
    for (int lt = 0; lt < 4; lt++) {
        int l0 = ls * 128 + lt * 32;
        for (int i = tid; i < 512; i += 256) {
            int c = i / 8, w = (i % 8) * 4;
            float4 v = *(const float4*)(f2 + (size_t)c * LPAD + l0 + w);
            Fs[c][w] = v.x; Fs[c][w + 1] = v.y; Fs[c][w + 2] = v.z; Fs[c][w + 3] = v.w;
        }
        __syncthreads();
#pragma unroll 8
        for (int j = 0; j < 32; j++) {
            float a[4], bv[4];
#pragma unroll
            for (int i = 0; i < 4; i++) a[i] = Fs[cy + i][j];
#pragma unroll
            for (int i = 0; i < 4; i++) bv[i] = Fs[dx + i][j];
#pragma unroll
            for (int i = 0; i < 4; i++)
#pragma unroll
                for (int jj = 0; jj < 4; jj++) acc[i][jj] += a[i] * bv[jj];
        }
        __syncthreads();
    }
#pragma unroll
    for (int i = 0; i < 4; i++)
#pragma unroll
        for (int jj = 0; jj < 4; jj++)
            atomicAdd(&g_came[b * 4096 + (cy + i) * 64 + dx + jj], acc[i][jj]);
}

// ---------- CAM: softmax (folded) + out GEMM + epilogue ----------
__global__ __launch_bounds__(256) void k_camout(const float* __restrict__ gamma) {
    int b = blockIdx.y, l0 = blockIdx.x * 64;
    __shared__ float As[64][65], Fs[64][68];
    int tid = threadIdx.x;
    const float* f2 = g_feat2 + (size_t)b * IC * LPAD;
    for (int i = tid; i < 4096; i += 256) As[i / 64][i % 64] = g_came[b * 4096 + i];
    for (int i = tid; i < 1024; i += 256) {
        int d = i / 16, w = (i % 16) * 4;
        float4 v = *(const float4*)(f2 + (size_t)d * LPAD + l0 + w);
        Fs[d][w] = v.x; Fs[d][w + 1] = v.y; Fs[d][w + 2] = v.z; Fs[d][w + 3] = v.w;
    }
    __syncthreads();
    {
        int r = tid / 4, q = tid % 4;
        float e[16];
        float mn = 1e30f;
#pragma unroll
        for (int k = 0; k < 16; k++) { e[k] = As[r][q * 16 + k]; mn = fminf(mn, e[k]); }
        mn = fminf(mn, __shfl_xor_sync(0xffffffffu, mn, 1));
        mn = fminf(mn, __shfl_xor_sync(0xffffffffu, mn, 2));
        float s = 0.f;
#pragma unroll
        for (int k = 0; k < 16; k++) { e[k] = __expf(mn - e[k]); s += e[k]; }
        s += __shfl_xor_sync(0xffffffffu, s, 1);
        s += __shfl_xor_sync(0xffffffffu, s, 2);
        float inv = 1.f / s;
#pragma unroll
        for (int k = 0; k < 16; k++) As[r][q * 16 + k] = e[k] * inv;
    }
    __syncthreads();
    int cy = (tid / 16) * 4, lx = (tid % 16) * 4;
    u64 acc[4][2] = {};
#pragma unroll 4
    for (int d = 0; d < 64; d++) {
        u64 b01 = *(u64*)&Fs[d][lx];
        u64 b23 = *(u64*)&Fs[d][lx + 2];
#pragma unroll
        for (int i = 0; i < 4; i++) {
            float a = As[cy + i][d];
            u64 ap = pk2(a, a);
            fma2(acc[i][0], ap, b01);
            fma2(acc[i][1], ap, b23);
        }
    }
    float gm = gamma[0];
#pragma unroll
    for (int i = 0; i < 4; i++) {
        size_t row = ((size_t)b * IC + cy + i) * LPAD + l0 + lx;
        float2 a0 = up2(acc[i][0]), a1 = up2(acc[i][1]);
        float4 f = *(const float4*)(f2 + (size_t)(cy + i) * LPAD + l0 + lx);
        float4 r;
        r.x = gm * a0.x + f.x; r.y = gm * a0.y + f.y;
        r.z = gm * a1.x + f.z; r.w = gm * a1.y + f.w;
        *(float4*)(g_scfeat + row) = r;
    }
}

// ---------- conv3 pad1 (64 -> 64), f32x2, fused BN stats ----------
__global__ __launch_bounds__(256) void k_conv3(int fsel, const float* __restrict__ W, int osel, int slot) {
    const float* f = selbuf(fsel);
    float* out = selbuf(osel);
    int b = blockIdx.y, l0 = blockIdx.x * 128;
    __shared__ float Fs[16][134], Ws2[16][194];
    int tid = threadIdx.x;
    int og = tid / 32, lg = tid % 32;
    u64 acc[8][2] = {};
    const float* fb = f + (size_t)b * IC * LPAD;
    for (int c0 = 0; c0 < 64; c0 += 16) {
        for (int i = tid; i < 2080; i += 256) {
            int cc = i / 130, j = i % 130;
            int gl = l0 + j - 1;
            Fs[cc][j] = (gl >= 0 && gl < LPAD) ? fb[(size_t)(c0 + cc) * LPAD + gl] : 0.f;
        }
        for (int i = tid; i < 3072; i += 256) {
            int o = i / 48, r = i % 48;
            Ws2[r / 3][o * 3 + (r % 3)] = W[o * 192 + c0 * 3 + r];
        }
        __syncthreads();
#pragma unroll
        for (int cc = 0; cc < 16; cc++) {
            float bv[6];
#pragma unroll
            for (int j = 0; j < 6; j++) bv[j] = Fs[cc][lg * 4 + j];
            u64 A = pk2(bv[0], bv[1]), Bp = pk2(bv[1], bv[2]), C = pk2(bv[2], bv[3]);
            u64 D = pk2(bv[3], bv[4]), E = pk2(bv[4], bv[5]);
#pragma unroll
            for (int oi = 0; oi < 8; oi++) {
                int o = og * 8 + oi;
                float w0 = Ws2[cc][o * 3], w1 = Ws2[cc][o * 3 + 1], w2 = Ws2[cc][o * 3 + 2];
                u64 w0d = pk2(w0, w0), w1d = pk2(w1, w1), w2d = pk2(w2, w2);
                fma2(acc[oi][0], w0d, A); fma2(acc[oi][0], w1d, Bp); fma2(acc[oi][0], w2d, C);
                fma2(acc[oi][1], w0d, C); fma2(acc[oi][1], w1d, D);  fma2(acc[oi][1], w2d, E);
            }
        }
        __syncthreads();
    }
#pragma unroll
    for (int oi = 0; oi < 8; oi++) {
        float2 x0 = up2(acc[oi][0]), x1 = up2(acc[oi][1]);
        float4 r; r.x = x0.x; r.y = x0.y; r.z = x1.x; r.w = x1.y;
        *(float4*)(out + ((size_t)b * IC + og * 8 + oi) * LPAD + l0 + lg * 4) = r;
        float s = r.x + r.y + r.z + r.w;
        float ss = r.x * r.x + r.y * r.y + r.z * r.z + r.w * r.w;
#pragma unroll
        for (int off = 16; off > 0; off >>= 1) {
            s  += __shfl_xor_sync(0xffffffffu, s, off);
            ss += __shfl_xor_sync(0xffffffffu, ss, off);
        }
        if (lg == 0) {
            atomicAdd(&g_sS[slot * IC + og * 8 + oi], s);
            atomicAdd(&g_sSS[slot * IC + og * 8 + oi], ss);
        }
    }
}

// ---------- final 1x1 conv: all 128 outputs per block ----------
__global__ __launch_bounds__(256) void k_out1x1(int ssel, const float* __restrict__ W,
                                                const float* __restrict__ bias,
                                                float* __restrict__ dst) {
    const float* src = selbuf(ssel);
    int b = blockIdx.z, l0 = blockIdx.x * 64;
    __shared__ float Ws[16][132], Xs[16][68];
    int tid = threadIdx.x, ty = tid / 16, tx = tid % 16;   // o = ty*8.., l = tx*4..
    u64 acc[8][2] = {};
    const float* sb = src + (size_t)b * IC * LPAD;
    for (int kc = 0; kc < 64; kc += 16) {
#pragma unroll
        for (int t = 0; t < 8; t++) {
            int i = tid + t * 256, k = i / 128, o = i % 128;
            Ws[k][o] = W[o * 64 + kc + k];
        }
        {
            int k = tid / 16, l4 = (tid % 16) * 4;
            float4 v = *(const float4*)(sb + (size_t)(kc + k) * LPAD + l0 + l4);
            Xs[k][l4] = v.x; Xs[k][l4 + 1] = v.y; Xs[k][l4 + 2] = v.z; Xs[k][l4 + 3] = v.w;
        }
        __syncthreads();
#pragma unroll
        for (int k = 0; k < 16; k++) {
            float4 a0 = *(float4*)&Ws[k][ty * 8];
            float4 a1 = *(float4*)&Ws[k][ty * 8 + 4];
            u64 b01 = *(u64*)&Xs[k][tx * 4];
            u64 b23 = *(u64*)&Xs[k][tx * 4 + 2];
            u64 d0 = pk2(a0.x, a0.x), d1 = pk2(a0.y, a0.y), d2 = pk2(a0.z, a0.z), d3 = pk2(a0.w, a0.w);
            u64 d4 = pk2(a1.x, a1.x), d5 = pk2(a1.y, a1.y), d6 = pk2(a1.z, a1.z), d7 = pk2(a1.w, a1.w);
            fma2(acc[0][0], d0, b01); fma2(acc[0][1], d0, b23);
            fma2(acc[1][0], d1, b01); fma2(acc[1][1], d1, b23);
            fma2(acc[2][0], d2, b01); fma2(acc[2][1], d2, b23);
            fma2(acc[3][0], d3, b01); fma2(acc[3][1], d3, b23);
            fma2(acc[4][0], d4, b01); fma2(acc[4][1], d4, b23);
            fma2(acc[5][0], d5, b01); fma2(acc[5][1], d5, b23);
            fma2(acc[6][0], d6, b01); fma2(acc[6][1], d6, b23);
            fma2(acc[7][0], d7, b01); fma2(acc[7][1], d7, b23);
        }
        __syncthreads();
    }
#pragma unroll
    for (int i = 0; i < 8; i++) {
        int o = ty * 8 + i;
        float bs = bias[o];
        float2 p0 = up2(acc[i][0]), p1 = up2(acc[i][1]);
        float4 r; r.x = p0.x + bs; r.y = p0.y + bs; r.z = p1.x + bs; r.w = p1.y + bs;
        *(float4*)(dst + ((size_t)b * OCH + o) * LPAD + l0 + tx * 4) = r;
    }
}

// ---------- column mean of (saconv + scconv) ----------
__global__ void k_colmean() {
    int b = blockIdx.x / IC, c = blockIdx.x % IC;
    const float4* p1 = (const float4*)(g_saconv + ((size_t)b * IC + c) * LPAD);
    const float4* p2 = (const float4*)(g_scconv + ((size_t)b * IC + c) * LPAD);
    float s = 0.f;
    for (int l = threadIdx.x; l < LPAD / 4; l += 128) {
        float4 a = p1[l], bq = p2[l];
        s += a.x + a.y + a.z + a.w + bq.x + bq.y + bq.z + bq.w;
    }
#pragma unroll
    for (int off = 16; off > 0; off >>= 1) s += __shfl_xor_sync(0xffffffffu, s, off);
    __shared__ float red[4];
    int lane = threadIdx.x & 31, wid = threadIdx.x >> 5;
    if (lane == 0) red[wid] = s;
    __syncthreads();
    if (threadIdx.x == 0)
        g_msum[b * IC + c] = (red[0] + red[1] + red[2] + red[3]) / (float)LPAD;
}

__global__ void k_sasc(const float* __restrict__ W8, const float* __restrict__ b8,
                       float* __restrict__ dout) {
    int b = blockIdx.x, o = threadIdx.x;
    float s = b8[o];
    for (int c = 0; c < IC; c++) s += W8[o * IC + c] * g_msum[b * IC + c];
    dout[b * OCH + o] = s;
}

extern "C" void kernel_launch(void* const* d_in, const int* in_sizes, int n_in,
                              void* d_out, int out_size) {
    const float* x   = (const float*)d_in[0];
    const float* W5a = (const float*)d_in[1];
    const float* g5a = (const float*)d_in[2];
    const float* b5a = (const float*)d_in[3];
    const float* W5c = (const float*)d_in[4];
    const float* g5c = (const float*)d_in[5];
    const float* b5c = (const float*)d_in[6];
    const float* Wq  = (const float*)d_in[7];
    const float* bq  = (const float*)d_in[8];
    const float* Wk  = (const float*)d_in[9];
    const float* bk  = (const float*)d_in[10];
    const float* Wv  = (const float*)d_in[11];
    const float* bv  = (const float*)d_in[12];
    const float* gpam = (const float*)d_in[13];
    const float* gcam = (const float*)d_in[14];
    const float* W51 = (const float*)d_in[15];
    const float* g51 = (const float*)d_in[16];
    const float* b51 = (const float*)d_in[17];
    const float* W52 = (const float*)d_in[18];
    const float* g52 = (const float*)d_in[19];
    const float* b52 = (const float*)d_in[20];
    const float* W6  = (const float*)d_in[21];
    const float* b6  = (const float*)d_in[22];
    const float* W7  = (const float*)d_in[23];
    const float* b7  = (const float*)d_in[24];
    const float* W8  = (const float*)d_in[25];
    const float* b8  = (const float*)d_in[26];
    float* out = (float*)d_out;
    const size_t OUTSZ = (size_t)BB * OCH * LPAD;

    k_zeroall<<<131, 256>>>();
    k_convx<<<dim3(32, 1, BB), 256>>>(x, W5a, W5c);
    k_bnrelu01<<<dim3(1024, 1, 2), 256>>>(g5a, b5a, g5c, b5c);

    // PAM branch
    k_qkv<<<dim3(32, BB), 256>>>(Wq, bq, Wk, bk, Wv, bv);
    k_pamout<<<dim3(16, BB), 256>>>(gpam);
    k_conv3<<<dim3(16, BB), 256>>>(8, W51, 2, 2);
    k_bnrelu<<<1024, 256>>>(2, 6, g51, b51, 2);
    k_out1x1<<<dim3(32, 1, BB), 256>>>(6, W6, b6, out + BB * OCH);

    // CAM branch
    k_came<<<dim3(BB, 16), 256>>>();
    k_camout<<<dim3(32, BB), 256>>>(gcam);
    k_conv3<<<dim3(16, BB), 256>>>(9, W52, 3, 3);
    k_bnrelu<<<1024, 256>>>(3, 7, g52, b52, 3);
    k_out1x1<<<dim3(32, 1, BB), 256>>>(7, W7, b7, out + BB * OCH + OUTSZ);

    // fused mean path
    k_colmean<<<BB * IC, 128>>>();
    k_sasc<<<BB, OCH>>>(W8, b8, out);
}

// round 14
// speedup vs baseline: 1.1880x; 1.1880x over previous
#include <cuda_runtime.h>
#include <math.h>

#define BB   8
#define CIN  256
#define LIN  2046
#define LPAD 2048
#define IC   64
#define OCH  128
#define BNEPS 1e-5f
#define MT   32

typedef unsigned long long u64;
__device__ __forceinline__ u64 pk2(float x, float y) { u64 r; asm("mov.b64 %0,{%1,%2};" : "=l"(r) : "f"(x), "f"(y)); return r; }
__device__ __forceinline__ float2 up2(u64 v) { float2 r; asm("mov.b64 {%0,%1},%2;" : "=f"(r.x), "=f"(r.y) : "l"(v)); return r; }
__device__ __forceinline__ void fma2(u64& d, u64 a, u64 b) { asm("fma.rn.f32x2 %0,%1,%2,%0;" : "+l"(d) : "l"(a), "l"(b)); }

// ---------------- scratch ----------------
__device__ float g_pre1[BB*IC*LPAD];
__device__ float g_pre2[BB*IC*LPAD];
__device__ float g_preA[BB*IC*LPAD];
__device__ float g_preB[BB*IC*LPAD];
__device__ float g_feat1[BB*IC*LPAD];
__device__ float g_feat2[BB*IC*LPAD];
__device__ float g_saconv[BB*IC*LPAD];
__device__ float g_scconv[BB*IC*LPAD];
__device__ float g_safeat[BB*IC*LPAD];
__device__ float g_scfeat[BB*IC*LPAD];
__device__ float g_qp[BB*8*LPAD];
__device__ float g_kp[BB*8*LPAD];
__device__ float g_v[BB*IC*LPAD];
__device__ float g_psumA[BB*LPAD];
__device__ float g_psumB[BB*LPAD];
__device__ float g_came[BB*IC*IC];
__device__ float g_msum[BB*IC];
__device__ float g_sS[4*IC];
__device__ float g_sSS[4*IC];
__device__ unsigned g_kmax[BB*8];

__device__ __forceinline__ float* selbuf(int s) {
    switch (s) {
        case 0: return g_pre1;   case 1: return g_pre2;
        case 2: return g_preA;   case 3: return g_preB;
        case 4: return g_feat1;  case 5: return g_feat2;
        case 6: return g_saconv; case 7: return g_scconv;
        case 8: return g_safeat; default: return g_scfeat;
    }
}

__global__ void k_zeroall() {
    int idx = blockIdx.x * 256 + threadIdx.x;
    if (idx < BB*IC*IC) g_came[idx] = 0.f;
    if (idx < 4*IC) { g_sS[idx] = 0.f; g_sSS[idx] = 0.f; }
    if (idx < BB*8) g_kmax[idx] = 0u;
}

// ---------- conv1x1 from x: one block does ALL 128 outputs for a 64-l tile ----------
__global__ __launch_bounds__(256) void k_convx(const float* __restrict__ x,
                                               const float* __restrict__ W5a,
                                               const float* __restrict__ W5c) {
    int b = blockIdx.z, l0 = blockIdx.x * 64;
    __shared__ float Ws[16][132], Xs[16][68];
    int tid = threadIdx.x, ty = tid / 16, tx = tid % 16;
    u64 acc[8][2] = {};
    const float* xb = x + (size_t)b * CIN * LIN;
    for (int kc = 0; kc < CIN; kc += 16) {
#pragma unroll
        for (int t = 0; t < 8; t++) {
            int i = tid + t * 256, k = i / 128, o = i % 128;
            const float* Wp = (o < IC) ? (W5a + o * CIN) : (W5c + (o - IC) * CIN);
            Ws[k][o] = Wp[kc + k];
        }
#pragma unroll
        for (int t = 0; t < 4; t++) {
            int i = tid + t * 256, k = i / 64, l = i % 64;
            int gl = l0 + l;
            Xs[k][l] = (gl < LIN) ? xb[(size_t)(kc + k) * LIN + gl] : 0.f;
        }
        __syncthreads();
#pragma unroll
        for (int k = 0; k < 16; k++) {
            float4 a0 = *(float4*)&Ws[k][ty * 8];
            float4 a1 = *(float4*)&Ws[k][ty * 8 + 4];
            u64 b01 = *(u64*)&Xs[k][tx * 4];
            u64 b23 = *(u64*)&Xs[k][tx * 4 + 2];
            u64 d0 = pk2(a0.x, a0.x), d1 = pk2(a0.y, a0.y), d2 = pk2(a0.z, a0.z), d3 = pk2(a0.w, a0.w);
            u64 d4 = pk2(a1.x, a1.x), d5 = pk2(a1.y, a1.y), d6 = pk2(a1.z, a1.z), d7 = pk2(a1.w, a1.w);
            fma2(acc[0][0], d0, b01); fma2(acc[0][1], d0, b23);
            fma2(acc[1][0], d1, b01); fma2(acc[1][1], d1, b23);
            fma2(acc[2][0], d2, b01); fma2(acc[2][1], d2, b23);
            fma2(acc[3][0], d3, b01); fma2(acc[3][1], d3, b23);
            fma2(acc[4][0], d4, b01); fma2(acc[4][1], d4, b23);
            fma2(acc[5][0], d5, b01); fma2(acc[5][1], d5, b23);
            fma2(acc[6][0], d6, b01); fma2(acc[6][1], d6, b23);
            fma2(acc[7][0], d7, b01); fma2(acc[7][1], d7, b23);
        }
        __syncthreads();
    }
#pragma unroll
    for (int i = 0; i < 8; i++) {
        int o = ty * 8 + i;
        int slot = (o < IC) ? 0 : 1;
        int ch = o & (IC - 1);
        float* dst = (o < IC) ? (g_pre1 + ((size_t)b * IC + ch) * LPAD)
                              : (g_pre2 + ((size_t)b * IC + ch) * LPAD);
        float2 p0 = up2(acc[i][0]), p1 = up2(acc[i][1]);
        float vv[4] = {p0.x, p0.y, p1.x, p1.y};
        float s = 0.f, ss = 0.f;
#pragma unroll
        for (int j = 0; j < 4; j++) {
            int l = l0 + tx * 4 + j;
            if (l < LIN) { dst[l + 1] = vv[j]; s += vv[j]; ss += vv[j] * vv[j]; }
        }
#pragma unroll
        for (int off = 8; off > 0; off >>= 1) {
            s  += __shfl_xor_sync(0xffffffffu, s, off);
            ss += __shfl_xor_sync(0xffffffffu, ss, off);
        }
        if (tx == 0) {
            atomicAdd(&g_sS[slot * IC + ch], s);
            atomicAdd(&g_sSS[slot * IC + ch], ss);
        }
    }
}

// ---------- BN + ReLU (float4), dual-slot via grid.z ----------
__global__ void k_bnrelu01(const float* __restrict__ g0, const float* __restrict__ bia0,
                           const float* __restrict__ g1, const float* __restrict__ bia1) {
    int z = blockIdx.z;
    const float4* pre = (const float4*)selbuf(z);
    float4* out = (float4*)selbuf(4 + z);
    const float* g = z ? g1 : g0;
    const float* bia = z ? bia1 : bia0;
    int idx = blockIdx.x * 256 + threadIdx.x;
    int l4 = idx & 511;
    int c = (idx >> 9) & (IC - 1);
    float4 v = pre[idx];
    if (l4 == 0) v.x = 0.f;
    if (l4 == 511) v.w = 0.f;
    float N = (float)(BB * LPAD);
    float mu = g_sS[z * IC + c] / N;
    float rs = rsqrtf(g_sSS[z * IC + c] / N - mu * mu + BNEPS);
    float sc = rs * g[c], sb = bia[c] - mu * sc;
    float4 r;
    r.x = fmaxf(v.x * sc + sb, 0.f); r.y = fmaxf(v.y * sc + sb, 0.f);
    r.z = fmaxf(v.z * sc + sb, 0.f); r.w = fmaxf(v.w * sc + sb, 0.f);
    out[idx] = r;
}

__global__ void k_bnrelu(int psel, int osel, const float* __restrict__ g,
                         const float* __restrict__ bia, int slot) {
    const float4* pre = (const float4*)selbuf(psel);
    float4* out = (float4*)selbuf(osel);
    int idx = blockIdx.x * 256 + threadIdx.x;
    int c = (idx >> 9) & (IC - 1);
    float4 v = pre[idx];
    float N = (float)(BB * LPAD);
    float mu = g_sS[slot * IC + c] / N;
    float rs = rsqrtf(g_sSS[slot * IC + c] / N - mu * mu + BNEPS);
    float sc = rs * g[c], sb = bia[c] - mu * sc;
    float4 r;
    r.x = fmaxf(v.x * sc + sb, 0.f); r.y = fmaxf(v.y * sc + sb, 0.f);
    r.z = fmaxf(v.z * sc + sb, 0.f); r.w = fmaxf(v.w * sc + sb, 0.f);
    out[idx] = r;
}

// ---------- q/k/v: l-tile 32, single smem phase, 512 CTAs ----------
__global__ __launch_bounds__(256) void k_qkv(const float* __restrict__ Wq, const float* __restrict__ bq,
                                             const float* __restrict__ Wk, const float* __restrict__ bk,
                                             const float* __restrict__ Wv, const float* __restrict__ bvw) {
    int b = blockIdx.y, l0 = blockIdx.x * 32;
    __shared__ float Ws[64][81];   // [k][o]
    __shared__ float Xs[64][34];   // [k][l]
    int tid = threadIdx.x;
    const float* f1 = g_feat1 + (size_t)b * IC * LPAD;
#pragma unroll
    for (int t = 0; t < 5; t++) {
        int i4 = tid + t * 256;            // 0..1279
        int o = i4 >> 4, k4 = (i4 & 15) * 4;
        const float* src = (o < 8) ? (Wq + o * IC) : ((o < 16) ? (Wk + (o - 8) * IC) : (Wv + (o - 16) * IC));
        float4 v = *(const float4*)(src + k4);
        Ws[k4 + 0][o] = v.x; Ws[k4 + 1][o] = v.y; Ws[k4 + 2][o] = v.z; Ws[k4 + 3][o] = v.w;
    }
#pragma unroll
    for (int t = 0; t < 2; t++) {
        int i4 = tid + t * 256;            // 0..511
        int k = i4 >> 3, l4 = (i4 & 7) * 4;
        float4 v = *(const float4*)(f1 + (size_t)k * LPAD + l0 + l4);
        Xs[k][l4] = v.x; Xs[k][l4 + 1] = v.y; Xs[k][l4 + 2] = v.z; Xs[k][l4 + 3] = v.w;
    }
    __syncthreads();
    int o0 = (tid >> 4) * 5, lx = (tid & 15) * 2;
    u64 acc[5] = {};
#pragma unroll 8
    for (int k = 0; k < 64; k++) {
        u64 xv = *(u64*)&Xs[k][lx];
        float w0 = Ws[k][o0], w1 = Ws[k][o0 + 1], w2 = Ws[k][o0 + 2], w3 = Ws[k][o0 + 3], w4 = Ws[k][o0 + 4];
        fma2(acc[0], pk2(w0, w0), xv);
        fma2(acc[1], pk2(w1, w1), xv);
        fma2(acc[2], pk2(w2, w2), xv);
        fma2(acc[3], pk2(w3, w3), xv);
        fma2(acc[4], pk2(w4, w4), xv);
    }
#pragma unroll
    for (int i = 0; i < 5; i++) {
        int o = o0 + i;
        float bias = (o < 8) ? bq[o] : ((o < 16) ? bk[o - 8] : bvw[o - 16]);
        float2 p = up2(acc[i]);
        float2 r = {p.x + bias, p.y + bias};
        float* base = (o < 8) ? (g_qp + (size_t)(b * 8 + o) * LPAD)
                    : ((o < 16) ? (g_kp + (size_t)(b * 8 + o - 8) * LPAD)
                                : (g_v + ((size_t)b * IC + o - 16) * LPAD));
        *(float2*)(base + l0 + lx) = r;
        float ka = fmaxf(fabsf(r.x), fabsf(r.y));
        ka = fmaxf(ka, __shfl_xor_sync(0xffffffffu, ka, 1));
        ka = fmaxf(ka, __shfl_xor_sync(0xffffffffu, ka, 2));
        ka = fmaxf(ka, __shfl_xor_sync(0xffffffffu, ka, 4));
        ka = fmaxf(ka, __shfl_xor_sync(0xffffffffu, ka, 8));
        if ((tid & 15) == 0 && o >= 8 && o < 16)
            atomicMax(&g_kmax[b * 8 + (o - 8)], __float_as_uint(ka));
    }
}

// ---------- PAM fused, split-m over grid.z (partials, no normalize) ----------
__global__ __launch_bounds__(256) void k_pamout() {
    int b = blockIdx.y, l0 = blockIdx.x * 128, z = blockIdx.z;   // grid (16, 8, 2)
    __shared__ u64  ksp[4][36];
    __shared__ float psT[MT][132];
    __shared__ float vsmT[MT][68];
    __shared__ float sumP[2][128];
    int tid = threadIdx.x;
    int lq = tid & 127, mh = tid >> 7;
    float qj[8];
#pragma unroll
    for (int j = 0; j < 8; j++) qj[j] = g_qp[((size_t)(b * 8 + j)) * LPAD + l0 + lq];
    u64 qp[4] = { pk2(qj[0], qj[1]), pk2(qj[2], qj[3]), pk2(qj[4], qj[5]), pk2(qj[6], qj[7]) };
    float Mv = 0.f;
#pragma unroll
    for (int j = 0; j < 8; j++) Mv += fabsf(qj[j]) * __uint_as_float(g_kmax[b * 8 + j]);
    float lsum = 0.f;
    int cy = (tid >> 5) * 8, lx = (tid & 31) * 4;
    u64 acc[8][2] = {};
    const float* vb = g_v + (size_t)b * IC * LPAD;
    int mbase = z * 1024;
    for (int m0 = mbase; m0 < mbase + 1024; m0 += MT) {
        if (tid < 128) {
            int p = tid >> 5, m = tid & 31;
            float kx = g_kp[((size_t)(b * 8 + 2 * p)) * LPAD + m0 + m];
            float ky = g_kp[((size_t)(b * 8 + 2 * p + 1)) * LPAD + m0 + m];
            ksp[p][m] = pk2(kx, ky);
        }
#pragma unroll
        for (int t = 0; t < 2; t++) {
            int i = tid + t * 256;
            int c = i >> 3, m4 = (i & 7) * 4;
            float4 v = *(const float4*)(vb + (size_t)c * LPAD + m0 + m4);
            vsmT[m4 + 0][c] = v.x; vsmT[m4 + 1][c] = v.y;
            vsmT[m4 + 2][c] = v.z; vsmT[m4 + 3][c] = v.w;
        }
        __syncthreads();
#pragma unroll
        for (int t = 0; t < 16; t++) {
            int m = mh * 16 + t;
            u64 s2 = 0ull;
            fma2(s2, qp[0], ksp[0][m]); fma2(s2, qp[1], ksp[1][m]);
            fma2(s2, qp[2], ksp[2][m]); fma2(s2, qp[3], ksp[3][m]);
            float2 sv = up2(s2);
            float p = __expf(sv.x + sv.y - Mv);
            psT[m][lq] = p;
            lsum += p;
        }
        __syncthreads();
#pragma unroll 4
        for (int m = 0; m < MT; m++) {
            u64 p01 = *(u64*)&psT[m][lx];
            u64 p23 = *(u64*)&psT[m][lx + 2];
            float4 v0 = *(float4*)&vsmT[m][cy];
            float4 v1 = *(float4*)&vsmT[m][cy + 4];
            u64 d0 = pk2(v0.x, v0.x), d1 = pk2(v0.y, v0.y), d2 = pk2(v0.z, v0.z), d3 = pk2(v0.w, v0.w);
            u64 d4 = pk2(v1.x, v1.x), d5 = pk2(v1.y, v1.y), d6 = pk2(v1.z, v1.z), d7 = pk2(v1.w, v1.w);
            fma2(acc[0][0], d0, p01); fma2(acc[0][1], d0, p23);
            fma2(acc[1][0], d1, p01); fma2(acc[1][1], d1, p23);
            fma2(acc[2][0], d2, p01); fma2(acc[2][1], d2, p23);
            fma2(acc[3][0], d3, p01); fma2(acc[3][1], d3, p23);
            fma2(acc[4][0], d4, p01); fma2(acc[4][1], d4, p23);
            fma2(acc[5][0], d5, p01); fma2(acc[5][1], d5, p23);
            fma2(acc[6][0], d6, p01); fma2(acc[6][1], d6, p23);
            fma2(acc[7][0], d7, p01); fma2(acc[7][1], d7, p23);
        }
        __syncthreads();
    }
    sumP[mh][lq] = lsum;
    __syncthreads();
    if (tid < 128) {
        float s = sumP[0][tid] + sumP[1][tid];
        float* ps = z ? g_psumB : g_psumA;
        ps[b * LPAD + l0 + tid] = s;
    }
    float* part = z ? g_preB : g_preA;
#pragma unroll
    for (int i = 0; i < 8; i++) {
        size_t row = ((size_t)b * IC + cy + i) * LPAD + l0 + lx;
        float2 a0 = up2(acc[i][0]), a1 = up2(acc[i][1]);
        float4 r = {a0.x, a0.y, a1.x, a1.y};
        *(float4*)(part + row) = r;
    }
}

// ---------- PAM reduce: combine halves, normalize, add feat1 ----------
__global__ void k_pamred(const float* __restrict__ gamma) {
    int i = blockIdx.x * 256 + threadIdx.x;        // float4 index
    int b = i >> 15;                                // IC*LPAD/4 = 32768 per batch
    int l = (i & 511) * 4;
    float4 p0 = ((const float4*)g_preA)[i];
    float4 p1 = ((const float4*)g_preB)[i];
    float4 f  = ((const float4*)g_feat1)[i];
    float4 s0 = *(const float4*)(g_psumA + b * LPAD + l);
    float4 s1 = *(const float4*)(g_psumB + b * LPAD + l);
    float gm = gamma[0];
    float4 r;
    r.x = gm * (p0.x + p1.x) / (s0.x + s1.x) + f.x;
    r.y = gm * (p0.y + p1.y) / (s0.y + s1.y) + f.y;
    r.z = gm * (p0.z + p1.z) / (s0.z + s1.z) + f.z;
    r.w = gm * (p0.w + p1.w) / (s0.w + s1.w) + f.w;
    ((float4*)g_safeat)[i] = r;
}

// ---------- CAM energy ----------
__global__ __launch_bounds__(256) void k_came() {
    int b = blockIdx.x, ls = blockIdx.y;
    __shared__ float Fs[64][33];
    int tid = threadIdx.x;
    int cy = (tid / 16) * 4, dx = (tid % 16) * 4;
    float acc[4][4] = {};
    const float* f2 = g_feat2 + (size_t)b * IC * LPAD;
    for (int lt = 0; lt < 4; lt++) {
        int l0 = ls * 128 + lt * 32;
        for (int i = tid; i < 512; i += 256) {
            int c = i / 8, w = (i % 8) * 4;
            float4 v = *(const float4*)(f2 + (size_t)c * LPAD + l0 + w);
            Fs[c][w] = v.x; Fs[c][w + 1] = v.y; Fs[c][w + 2] = v.z; Fs[c][w + 3] = v.w;
        }
        __syncthreads();
#pragma unroll 8
        for (int j = 0; j < 32; j++) {
            float a[4], bv[4];
#pragma unroll
            for (int i = 0; i < 4; i++) a[i] = Fs[cy + i][j];
#pragma unroll
            for (int i = 0; i < 4; i++) bv[i] = Fs[dx + i][j];
#pragma unroll
            for (int i = 0; i < 4; i++)
#pragma unroll
                for (int jj = 0; jj < 4; jj++) acc[i][jj] += a[i] * bv[jj];
        }
        __syncthreads();
    }
#pragma unroll
    for (int i = 0; i < 4; i++)
#pragma unroll
        for (int jj = 0; jj < 4; jj++)
            atomicAdd(&g_came[b * 4096 + (cy + i) * 64 + dx + jj], acc[i][jj]);
}

// ---------- CAM: softmax (folded) + out GEMM + epilogue ----------
__global__ __launch_bounds__(256) void k_camout(const float* __restrict__ gamma) {
    int b = blockIdx.y, l0 = blockIdx.x * 64;
    __shared__ float As[64][65], Fs[64][68];
    int tid = threadIdx.x;
    const float* f2 = g_feat2 + (size_t)b * IC * LPAD;
    for (int i = tid; i < 4096; i += 256) As[i / 64][i % 64] = g_came[b * 4096 + i];
    for (int i = tid; i < 1024; i += 256) {
        int d = i / 16, w = (i % 16) * 4;
        float4 v = *(const float4*)(f2 + (size_t)d * LPAD + l0 + w);
        Fs[d][w] = v.x; Fs[d][w + 1] = v.y; Fs[d][w + 2] = v.z; Fs[d][w + 3] = v.w;
    }
    __syncthreads();
    {
        int r = tid / 4, q = tid % 4;
        float e[16];
        float mn = 1e30f;
#pragma unroll
        for (int k = 0; k < 16; k++) { e[k] = As[r][q * 16 + k]; mn = fminf(mn, e[k]); }
        mn = fminf(mn, __shfl_xor_sync(0xffffffffu, mn, 1));
        mn = fminf(mn, __shfl_xor_sync(0xffffffffu, mn, 2));
        float s = 0.f;
#pragma unroll
        for (int k = 0; k < 16; k++) { e[k] = __expf(mn - e[k]); s += e[k]; }
        s += __shfl_xor_sync(0xffffffffu, s, 1);
        s += __shfl_xor_sync(0xffffffffu, s, 2);
        float inv = 1.f / s;
#pragma unroll
        for (int k = 0; k < 16; k++) As[r][q * 16 + k] = e[k] * inv;
    }
    __syncthreads();
    int cy = (tid / 16) * 4, lx = (tid % 16) * 4;
    u64 acc[4][2] = {};
#pragma unroll 4
    for (int d = 0; d < 64; d++) {
        u64 b01 = *(u64*)&Fs[d][lx];
        u64 b23 = *(u64*)&Fs[d][lx + 2];
#pragma unroll
        for (int i = 0; i < 4; i++) {
            float a = As[cy + i][d];
            u64 ap = pk2(a, a);
            fma2(acc[i][0], ap, b01);
            fma2(acc[i][1], ap, b23);
        }
    }
    float gm = gamma[0];
#pragma unroll
    for (int i = 0; i < 4; i++) {
        size_t row = ((size_t)b * IC + cy + i) * LPAD + l0 + lx;
        float2 a0 = up2(acc[i][0]), a1 = up2(acc[i][1]);
        float4 f = *(const float4*)(f2 + (size_t)(cy + i) * LPAD + l0 + lx);
        float4 r;
        r.x = gm * a0.x + f.x; r.y = gm * a0.y + f.y;
        r.z = gm * a1.x + f.z; r.w = gm * a1.y + f.w;
        *(float4*)(g_scfeat + row) = r;
    }
}

// ---------- conv3 pad1 (64 -> 64), f32x2, fused BN stats ----------
__global__ __launch_bounds__(256) void k_conv3(int fsel, const float* __restrict__ W, int osel, int slot) {
    const float* f = selbuf(fsel);
    float* out = selbuf(osel);
    int b = blockIdx.y, l0 = blockIdx.x * 128;
    __shared__ float Fs[16][134], Ws2[16][194];
    int tid = threadIdx.x;
    int og = tid / 32, lg = tid % 32;
    u64 acc[8][2] = {};
    const float* fb = f + (size_t)b * IC * LPAD;
    for (int c0 = 0; c0 < 64; c0 += 16) {
        for (int i = tid; i < 2080; i += 256) {
            int cc = i / 130, j = i % 130;
            int gl = l0 + j - 1;
            Fs[cc][j] = (gl >= 0 && gl < LPAD) ? fb[(size_t)(c0 + cc) * LPAD + gl] : 0.f;
        }
        for (int i = tid; i < 3072; i += 256) {
            int o = i / 48, r = i % 48;
            Ws2[r / 3][o * 3 + (r % 3)] = W[o * 192 + c0 * 3 + r];
        }
        __syncthreads();
#pragma unroll
        for (int cc = 0; cc < 16; cc++) {
            float bv[6];
#pragma unroll
            for (int j = 0; j < 6; j++) bv[j] = Fs[cc][lg * 4 + j];
            u64 A = pk2(bv[0], bv[1]), Bp = pk2(bv[1], bv[2]), C = pk2(bv[2], bv[3]);
            u64 D = pk2(bv[3], bv[4]), E = pk2(bv[4], bv[5]);
#pragma unroll
            for (int oi = 0; oi < 8; oi++) {
                int o = og * 8 + oi;
                float w0 = Ws2[cc][o * 3], w1 = Ws2[cc][o * 3 + 1], w2 = Ws2[cc][o * 3 + 2];
                u64 w0d = pk2(w0, w0), w1d = pk2(w1, w1), w2d = pk2(w2, w2);
                fma2(acc[oi][0], w0d, A); fma2(acc[oi][0], w1d, Bp); fma2(acc[oi][0], w2d, C);
                fma2(acc[oi][1], w0d, C); fma2(acc[oi][1], w1d, D);  fma2(acc[oi][1], w2d, E);
            }
        }
        __syncthreads();
    }
#pragma unroll
    for (int oi = 0; oi < 8; oi++) {
        float2 x0 = up2(acc[oi][0]), x1 = up2(acc[oi][1]);
        float4 r; r.x = x0.x; r.y = x0.y; r.z = x1.x; r.w = x1.y;
        *(float4*)(out + ((size_t)b * IC + og * 8 + oi) * LPAD + l0 + lg * 4) = r;
        float s = r.x + r.y + r.z + r.w;
        float ss = r.x * r.x + r.y * r.y + r.z * r.z + r.w * r.w;
#pragma unroll
        for (int off = 16; off > 0; off >>= 1) {
            s  += __shfl_xor_sync(0xffffffffu, s, off);
            ss += __shfl_xor_sync(0xffffffffu, ss, off);
        }
        if (lg == 0) {
            atomicAdd(&g_sS[slot * IC + og * 8 + oi], s);
            atomicAdd(&g_sSS[slot * IC + og * 8 + oi], ss);
        }
    }
}

// ---------- final 1x1 conv: all 128 outputs per block ----------
__global__ __launch_bounds__(256) void k_out1x1(int ssel, const float* __restrict__ W,
                                                const float* __restrict__ bias,
                                                float* __restrict__ dst) {
    const float* src = selbuf(ssel);
    int b = blockIdx.z, l0 = blockIdx.x * 64;
    __shared__ float Ws[16][132], Xs[16][68];
    int tid = threadIdx.x, ty = tid / 16, tx = tid % 16;
    u64 acc[8][2] = {};
    const float* sb = src + (size_t)b * IC * LPAD;
    for (int kc = 0; kc < 64; kc += 16) {
#pragma unroll
        for (int t = 0; t < 8; t++) {
            int i = tid + t * 256, k = i / 128, o = i % 128;
            Ws[k][o] = W[o * 64 + kc + k];
        }
        {
            int k = tid / 16, l4 = (tid % 16) * 4;
            float4 v = *(const float4*)(sb + (size_t)(kc + k) * LPAD + l0 + l4);
            Xs[k][l4] = v.x; Xs[k][l4 + 1] = v.y; Xs[k][l4 + 2] = v.z; Xs[k][l4 + 3] = v.w;
        }
        __syncthreads();
#pragma unroll
        for (int k = 0; k < 16; k++) {
            float4 a0 = *(float4*)&Ws[k][ty * 8];
            float4 a1 = *(float4*)&Ws[k][ty * 8 + 4];
            u64 b01 = *(u64*)&Xs[k][tx * 4];
            u64 b23 = *(u64*)&Xs[k][tx * 4 + 2];
            u64 d0 = pk2(a0.x, a0.x), d1 = pk2(a0.y, a0.y), d2 = pk2(a0.z, a0.z), d3 = pk2(a0.w, a0.w);
            u64 d4 = pk2(a1.x, a1.x), d5 = pk2(a1.y, a1.y), d6 = pk2(a1.z, a1.z), d7 = pk2(a1.w, a1.w);
            fma2(acc[0][0], d0, b01); fma2(acc[0][1], d0, b23);
            fma2(acc[1][0], d1, b01); fma2(acc[1][1], d1, b23);
            fma2(acc[2][0], d2, b01); fma2(acc[2][1], d2, b23);
            fma2(acc[3][0], d3, b01); fma2(acc[3][1], d3, b23);
            fma2(acc[4][0], d4, b01); fma2(acc[4][1], d4, b23);
            fma2(acc[5][0], d5, b01); fma2(acc[5][1], d5, b23);
            fma2(acc[6][0], d6, b01); fma2(acc[6][1], d6, b23);
            fma2(acc[7][0], d7, b01); fma2(acc[7][1], d7, b23);
        }
        __syncthreads();
    }
#pragma unroll
    for (int i = 0; i < 8; i++) {
        int o = ty * 8 + i;
        float bs = bias[o];
        float2 p0 = up2(acc[i][0]), p1 = up2(acc[i][1]);
        float4 r; r.x = p0.x + bs; r.y = p0.y + bs; r.z = p1.x + bs; r.w = p1.y + bs;
        *(float4*)(dst + ((size_t)b * OCH + o) * LPAD + l0 + tx * 4) = r;
    }
}

// ---------- column mean of (saconv + scconv) ----------
__global__ void k_colmean() {
    int b = blockIdx.x / IC, c = blockIdx.x % IC;
    const float4* p1 = (const float4*)(g_saconv + ((size_t)b * IC + c) * LPAD);
    const float4* p2 = (const float4*)(g_scconv + ((size_t)b * IC + c) * LPAD);
    float s = 0.f;
    for (int l = threadIdx.x; l < LPAD / 4; l += 128) {
        float4 a = p1[l], bq = p2[l];
        s += a.x + a.y + a.z + a.w + bq.x + bq.y + bq.z + bq.w;
    }
#pragma unroll
    for (int off = 16; off > 0; off >>= 1) s += __shfl_xor_sync(0xffffffffu, s, off);
    __shared__ float red[4];
    int lane = threadIdx.x & 31, wid = threadIdx.x >> 5;
    if (lane == 0) red[wid] = s;
    __syncthreads();
    if (threadIdx.x == 0)
        g_msum[b * IC + c] = (red[0] + red[1] + red[2] + red[3]) / (float)LPAD;
}

__global__ void k_sasc(const float* __restrict__ W8, const float* __restrict__ b8,
                       float* __restrict__ dout) {
    int b = blockIdx.x, o = threadIdx.x;
    float s = b8[o];
    for (int c = 0; c < IC; c++) s += W8[o * IC + c] * g_msum[b * IC + c];
    dout[b * OCH + o] = s;
}

extern "C" void kernel_launch(void* const* d_in, const int* in_sizes, int n_in,
                              void* d_out, int out_size) {
    const float* x   = (const float*)d_in[0];
    const float* W5a = (const float*)d_in[1];
    const float* g5a = (const float*)d_in[2];
    const float* b5a = (const float*)d_in[3];
    const float* W5c = (const float*)d_in[4];
    const float* g5c = (const float*)d_in[5];
    const float* b5c = (const float*)d_in[6];
    const float* Wq  = (const float*)d_in[7];
    const float* bq  = (const float*)d_in[8];
    const float* Wk  = (const float*)d_in[9];
    const float* bk  = (const float*)d_in[10];
    const float* Wv  = (const float*)d_in[11];
    const float* bv  = (const float*)d_in[12];
    const float* gpam = (const float*)d_in[13];
    const float* gcam = (const float*)d_in[14];
    const float* W51 = (const float*)d_in[15];
    const float* g51 = (const float*)d_in[16];
    const float* b51 = (const float*)d_in[17];
    const float* W52 = (const float*)d_in[18];
    const float* g52 = (const float*)d_in[19];
    const float* b52 = (const float*)d_in[20];
    const float* W6  = (const float*)d_in[21];
    const float* b6  = (const float*)d_in[22];
    const float* W7  = (const float*)d_in[23];
    const float* b7  = (const float*)d_in[24];
    const float* W8  = (const float*)d_in[25];
    const float* b8  = (const float*)d_in[26];
    float* out = (float*)d_out;
    const size_t OUTSZ = (size_t)BB * OCH * LPAD;

    k_zeroall<<<131, 256>>>();
    k_convx<<<dim3(32, 1, BB), 256>>>(x, W5a, W5c);
    k_bnrelu01<<<dim3(1024, 1, 2), 256>>>(g5a, b5a, g5c, b5c);

    // PAM branch
    k_qkv<<<dim3(64, BB), 256>>>(Wq, bq, Wk, bk, Wv, bv);
    k_pamout<<<dim3(16, BB, 2), 256>>>();
    k_pamred<<<1024, 256>>>(gpam);
    k_conv3<<<dim3(16, BB), 256>>>(8, W51, 2, 2);
    k_bnrelu<<<1024, 256>>>(2, 6, g51, b51, 2);
    k_out1x1<<<dim3(32, 1, BB), 256>>>(6, W6, b6, out + BB * OCH);

    // CAM branch
    k_came<<<dim3(BB, 16), 256>>>();
    k_camout<<<dim3(32, BB), 256>>>(gcam);
    k_conv3<<<dim3(16, BB), 256>>>(9, W52, 3, 3);
    k_bnrelu<<<1024, 256>>>(3, 7, g52, b52, 3);
    k_out1x1<<<dim3(32, 1, BB), 256>>>(7, W7, b7, out + BB * OCH + OUTSZ);

    // fused mean path
    k_colmean<<<BB * IC, 128>>>();
    k_sasc<<<BB, OCH>>>(W8, b8, out);
}